// round 2
// baseline (speedup 1.0000x reference)
#include <cuda_runtime.h>
#include <float.h>

#define N 16384
#define H 64
#define EPSF 1e-8f
#define NBLK 128
#define TPB 128
#define NB 65536            // buckets = top 16 bits of order-preserving key
#define SCAN_T 1024
#define SCAN_C (NB / SCAN_T)  // 64 counts per scan thread

// ---------------- scratch (device globals; no allocation allowed) ------------
__device__ float g_sorted[N];
__device__ int   g_cnt[NB];   // zeroed by mlp_zero_kernel each replay
__device__ int   g_off[NB];   // exclusive prefix; mutated by scatter into end-offsets
__device__ float g_pmse[NBLK];
__device__ float g_pd2[NBLK];

// ---------------- helpers -----------------------------------------------------
__device__ __forceinline__ float warp_sum(float v) {
#pragma unroll
    for (int o = 16; o > 0; o >>= 1) v += __shfl_xor_sync(0xffffffffu, v, o);
    return v;
}
__device__ __forceinline__ float warp_max(float v) {
#pragma unroll
    for (int o = 16; o > 0; o >>= 1) v = fmaxf(v, __shfl_xor_sync(0xffffffffu, v, o));
    return v;
}
// order-preserving float -> uint key (total order == float order for non-NaN)
__device__ __forceinline__ unsigned int okey(float f) {
    unsigned int u = __float_as_uint(f);
    return (u & 0x80000000u) ? ~u : (u | 0x80000000u);
}

// ---------------- 1) MLP partials + zero the bucket counters -----------------
__global__ void mlp_zero_kernel(const float* __restrict__ x,
                                const float* __restrict__ tgt,
                                const float* __restrict__ w1,
                                const float* __restrict__ b1,
                                const float* __restrict__ w2,
                                const float* __restrict__ b2) {
    // zero g_cnt: 16384 threads x int4 = 65536 ints
    int gi = blockIdx.x * TPB + threadIdx.x;
    reinterpret_cast<int4*>(g_cnt)[gi] = make_int4(0, 0, 0, 0);

    __shared__ float sw1[H], sb1[H], sw2[H], sc2[H];
    __shared__ float red_mse[TPB / 32], red_d2[TPB / 32];

    int tid = threadIdx.x;
    if (tid < H) {
        float a = w1[tid];
        float c = w2[tid];
        sw1[tid] = a;
        sb1[tid] = b1[tid];
        sw2[tid] = c;
        sc2[tid] = -2.0f * c * a * a;   // coeff of t*(1-t^2) in d2y/dx2
    }
    __syncthreads();

    float xv = x[gi];
    float pred = b2[0];
    float d2 = 0.0f;
#pragma unroll
    for (int h = 0; h < H; ++h) {
        float t = tanhf(fmaf(xv, sw1[h], sb1[h]));
        pred = fmaf(sw2[h], t, pred);
        float g = t * fmaf(-t, t, 1.0f);        // t - t^3
        d2 = fmaf(sc2[h], g, d2);
    }
    float e = pred - tgt[gi];
    float vm = e * e;
    float vd = d2 * d2;

    vm = warp_sum(vm);
    vd = warp_sum(vd);
    if ((tid & 31) == 0) { red_mse[tid >> 5] = vm; red_d2[tid >> 5] = vd; }
    __syncthreads();
    if (tid < 32) {
        float m = (tid < TPB / 32) ? red_mse[tid] : 0.0f;
        float d = (tid < TPB / 32) ? red_d2[tid] : 0.0f;
        m = warp_sum(m);
        d = warp_sum(d);
        if (tid == 0) { g_pmse[blockIdx.x] = m; g_pd2[blockIdx.x] = d; }
    }
}

// ---------------- 2) histogram -------------------------------------------------
__global__ void hist_kernel(const float* __restrict__ x) {
    int i = blockIdx.x * blockDim.x + threadIdx.x;
    unsigned int b = okey(x[i]) >> 16;
    atomicAdd(&g_cnt[b], 1);
}

// ---------------- 3) exclusive scan of 65536 counts (1 block) ------------------
__global__ void scan_kernel() {
    __shared__ int warp_sums[32];
    int tid = threadIdx.x;
    int lane = tid & 31;
    int wid = tid >> 5;
    int base = tid * SCAN_C;

    // pass 1: per-thread total
    int tot = 0;
#pragma unroll 4
    for (int i = 0; i < SCAN_C; ++i) tot += g_cnt[base + i];

    // warp inclusive scan
    int inc = tot;
#pragma unroll
    for (int o = 1; o < 32; o <<= 1) {
        int nb = __shfl_up_sync(0xffffffffu, inc, o);
        if (lane >= o) inc += nb;
    }
    if (lane == 31) warp_sums[wid] = inc;
    __syncthreads();
    if (wid == 0) {
        int v = warp_sums[lane];
        int winc = v;
#pragma unroll
        for (int o = 1; o < 32; o <<= 1) {
            int nb = __shfl_up_sync(0xffffffffu, winc, o);
            if (lane >= o) winc += nb;
        }
        warp_sums[lane] = winc - v;   // exclusive warp offsets
    }
    __syncthreads();

    int excl = warp_sums[wid] + (inc - tot);  // exclusive base for this thread

    // pass 2: re-read counts, write exclusive prefix
    int run = excl;
#pragma unroll 4
    for (int i = 0; i < SCAN_C; ++i) {
        int c = g_cnt[base + i];
        g_off[base + i] = run;
        run += c;
    }
}

// ---------------- 4) scatter ----------------------------------------------------
__global__ void scatter_kernel(const float* __restrict__ x) {
    int i = blockIdx.x * blockDim.x + threadIdx.x;
    float xv = x[i];
    unsigned int b = okey(xv) >> 16;
    int pos = atomicAdd(&g_off[b], 1);
    g_sorted[pos] = xv;
}

// ---------------- 5) per-bucket insertion sort ----------------------------------
__global__ void segsort_kernel() {
    int b = blockIdx.x * blockDim.x + threadIdx.x;  // one thread per bucket
    // post-scatter, g_off[b] == end offset of bucket b; start == end of bucket b-1
    int start = (b == 0) ? 0 : g_off[b - 1];
    int end = g_off[b];
    for (int i = start + 1; i < end; ++i) {
        float v = g_sorted[i];
        int j = i - 1;
        while (j >= start && g_sorted[j] > v) {
            g_sorted[j + 1] = g_sorted[j];
            --j;
        }
        g_sorted[j + 1] = v;
    }
}

// ---------------- 6) density + finalize (1 block, 1024 threads) -----------------
__global__ void density_finalize_kernel(float* __restrict__ out) {
    __shared__ float r_sum[32], r_max[32], r_mse[32], r_d2[32];
    int tid = threadIdx.x;
    int lane = tid & 31;
    int wid = tid >> 5;

    float dsum = 0.0f, dmax = -FLT_MAX;
#pragma unroll
    for (int i = tid; i < N; i += 1024) {
        float xi = g_sorted[i];
        float c0 = (i >= 1)     ? xi - g_sorted[i - 1] : FLT_MAX;
        float c1 = (i >= 2)     ? xi - g_sorted[i - 2] : FLT_MAX;
        float c2 = (i + 1 < N)  ? g_sorted[i + 1] - xi : FLT_MAX;
        float c3 = (i + 2 < N)  ? g_sorted[i + 2] - xi : FLT_MAX;
        float m1 = fminf(c0, c2);
        float m2 = (c0 < c2) ? fminf(c1, c2) : fminf(c0, c3);
        // knn vals = {EPS, m1+EPS, m2+EPS}; mean = (m1+m2)/3 + EPS
        float knn_mean = (m1 + m2 + 3.0f * EPSF) * (1.0f / 3.0f);
        float dens = 1.0f / (knn_mean + EPSF);
        dsum += dens;
        dmax = fmaxf(dmax, dens);
    }

    float vm = (tid < NBLK) ? g_pmse[tid] : 0.0f;
    float vd = (tid < NBLK) ? g_pd2[tid] : 0.0f;

    dsum = warp_sum(dsum);
    dmax = warp_max(dmax);
    vm = warp_sum(vm);
    vd = warp_sum(vd);
    if (lane == 0) { r_sum[wid] = dsum; r_max[wid] = dmax; r_mse[wid] = vm; r_d2[wid] = vd; }
    __syncthreads();
    if (wid == 0) {
        float s = r_sum[lane];
        float x2 = r_max[lane];
        float m = r_mse[lane];
        float d = r_d2[lane];
        s = warp_sum(s);
        x2 = warp_max(x2);
        m = warp_sum(m);
        d = warp_sum(d);
        if (lane == 0) {
            float mse = m * (1.0f / N);
            float md2 = d * (1.0f / N);
            float mean_dnorm = (s * (1.0f / N)) / (x2 + EPSF);
            float mean_w = 1.0f + 0.1f * mean_dnorm;
            float penalty = 0.01f * mean_w * md2;
            out[0] = mse + penalty;
            out[1] = mse;
            out[2] = penalty;
        }
    }
}

// ---------------- launch --------------------------------------------------------
extern "C" void kernel_launch(void* const* d_in, const int* in_sizes, int n_in,
                              void* d_out, int out_size) {
    const float* x   = (const float*)d_in[0];
    const float* tgt = (const float*)d_in[1];
    const float* w1  = (const float*)d_in[2];
    const float* b1  = (const float*)d_in[3];
    const float* w2  = (const float*)d_in[4];
    const float* b2  = (const float*)d_in[5];
    float* out = (float*)d_out;

    mlp_zero_kernel<<<NBLK, TPB>>>(x, tgt, w1, b1, w2, b2);  // also zeros g_cnt
    hist_kernel<<<64, 256>>>(x);
    scan_kernel<<<1, SCAN_T>>>();
    scatter_kernel<<<64, 256>>>(x);
    segsort_kernel<<<NB / 256, 256>>>();
    density_finalize_kernel<<<1, 1024>>>(out);
    (void)in_sizes; (void)n_in; (void)out_size;
}

// round 3
// speedup vs baseline: 1.1301x; 1.1301x over previous
#include <cuda_runtime.h>
#include <float.h>

#define N 16384
#define H 64
#define EPSF 1e-8f
#define NBLK 128
#define TPB 128
#define NB 65536            // buckets = top 16 bits of order-preserving key
#define SCAN_T 1024
#define SCAN_C (NB / SCAN_T)  // 64 counts per scan thread

// ---------------- scratch (device globals; no allocation allowed) ------------
__device__ float g_tmp[N];     // scattered (bucket-grouped) values
__device__ float g_sorted[N];  // fully sorted
__device__ int   g_cnt[NB];    // zeroed by mlp_zero_kernel each replay
__device__ int   g_off[NB];    // exclusive prefix; mutated by scatter
__device__ int   g_start[NB];  // pristine exclusive prefix (segment starts)
__device__ float g_pmse[NBLK];
__device__ float g_pd2[NBLK];

// ---------------- helpers -----------------------------------------------------
__device__ __forceinline__ float warp_sum(float v) {
#pragma unroll
    for (int o = 16; o > 0; o >>= 1) v += __shfl_xor_sync(0xffffffffu, v, o);
    return v;
}
__device__ __forceinline__ float warp_max(float v) {
#pragma unroll
    for (int o = 16; o > 0; o >>= 1) v = fmaxf(v, __shfl_xor_sync(0xffffffffu, v, o));
    return v;
}
// order-preserving float -> uint key (total order == float order for non-NaN)
__device__ __forceinline__ unsigned int okey(float f) {
    unsigned int u = __float_as_uint(f);
    return (u & 0x80000000u) ? ~u : (u | 0x80000000u);
}

// ---------------- 1) MLP partials + zero the bucket counters -----------------
__global__ void mlp_zero_kernel(const float* __restrict__ x,
                                const float* __restrict__ tgt,
                                const float* __restrict__ w1,
                                const float* __restrict__ b1,
                                const float* __restrict__ w2,
                                const float* __restrict__ b2) {
    // zero g_cnt: 16384 threads x int4 = 65536 ints
    int gi = blockIdx.x * TPB + threadIdx.x;
    reinterpret_cast<int4*>(g_cnt)[gi] = make_int4(0, 0, 0, 0);

    __shared__ float sw1[H], sb1[H], sw2[H], sc2[H];
    __shared__ float red_mse[TPB / 32], red_d2[TPB / 32];

    int tid = threadIdx.x;
    if (tid < H) {
        float a = w1[tid];
        float c = w2[tid];
        sw1[tid] = a;
        sb1[tid] = b1[tid];
        sw2[tid] = c;
        sc2[tid] = -2.0f * c * a * a;   // coeff of t*(1-t^2) in d2y/dx2
    }
    __syncthreads();

    float xv = x[gi];
    float pred = b2[0];
    float d2 = 0.0f;
#pragma unroll
    for (int h = 0; h < H; ++h) {
        float t = tanhf(fmaf(xv, sw1[h], sb1[h]));
        pred = fmaf(sw2[h], t, pred);
        float g = t * fmaf(-t, t, 1.0f);        // t - t^3
        d2 = fmaf(sc2[h], g, d2);
    }
    float e = pred - tgt[gi];
    float vm = e * e;
    float vd = d2 * d2;

    vm = warp_sum(vm);
    vd = warp_sum(vd);
    if ((tid & 31) == 0) { red_mse[tid >> 5] = vm; red_d2[tid >> 5] = vd; }
    __syncthreads();
    if (tid < 32) {
        float m = (tid < TPB / 32) ? red_mse[tid] : 0.0f;
        float d = (tid < TPB / 32) ? red_d2[tid] : 0.0f;
        m = warp_sum(m);
        d = warp_sum(d);
        if (tid == 0) { g_pmse[blockIdx.x] = m; g_pd2[blockIdx.x] = d; }
    }
}

// ---------------- 2) histogram -------------------------------------------------
__global__ void hist_kernel(const float* __restrict__ x) {
    int i = blockIdx.x * blockDim.x + threadIdx.x;
    unsigned int b = okey(x[i]) >> 16;
    atomicAdd(&g_cnt[b], 1);
}

// ---------------- 3) exclusive scan of 65536 counts (1 block) ------------------
__global__ void scan_kernel() {
    __shared__ int warp_sums[32];
    int tid = threadIdx.x;
    int lane = tid & 31;
    int wid = tid >> 5;
    int base = tid * SCAN_C;

    // pass 1: per-thread total (vectorized)
    int tot = 0;
#pragma unroll
    for (int i = 0; i < SCAN_C / 4; ++i) {
        int4 c4 = reinterpret_cast<const int4*>(g_cnt)[tid * (SCAN_C / 4) + i];
        tot += c4.x + c4.y + c4.z + c4.w;
    }

    // warp inclusive scan
    int inc = tot;
#pragma unroll
    for (int o = 1; o < 32; o <<= 1) {
        int nb = __shfl_up_sync(0xffffffffu, inc, o);
        if (lane >= o) inc += nb;
    }
    if (lane == 31) warp_sums[wid] = inc;
    __syncthreads();
    if (wid == 0) {
        int v = warp_sums[lane];
        int winc = v;
#pragma unroll
        for (int o = 1; o < 32; o <<= 1) {
            int nb = __shfl_up_sync(0xffffffffu, winc, o);
            if (lane >= o) winc += nb;
        }
        warp_sums[lane] = winc - v;   // exclusive warp offsets
    }
    __syncthreads();

    int excl = warp_sums[wid] + (inc - tot);  // exclusive base for this thread

    // pass 2: write exclusive prefix to BOTH g_off (mutable) and g_start (pristine)
    int run = excl;
#pragma unroll 4
    for (int i = 0; i < SCAN_C; ++i) {
        int c = g_cnt[base + i];
        g_off[base + i] = run;
        g_start[base + i] = run;
        run += c;
    }
}

// ---------------- 4) scatter (bucket-group, order within bucket arbitrary) ------
__global__ void scatter_kernel(const float* __restrict__ x) {
    int i = blockIdx.x * blockDim.x + threadIdx.x;
    float xv = x[i];
    unsigned int b = okey(xv) >> 16;
    int pos = atomicAdd(&g_off[b], 1);
    g_tmp[pos] = xv;
}

// ---------------- 5) parallel rank-in-segment (replaces serial insertion sort) --
__global__ void rank_kernel() {
    int p = blockIdx.x * blockDim.x + threadIdx.x;  // position in scattered array
    float v = g_tmp[p];
    unsigned int kv = okey(v);
    unsigned int b = kv >> 16;
    int start = g_start[b];
    int end = start + g_cnt[b];
    int rank = 0;
    for (int q = start; q < end; ++q) {
        unsigned int kq = okey(g_tmp[q]);
        // ties: equal key => bit-identical float; order among equals irrelevant,
        // but tie-break on q<p keeps ranks a permutation (no collisions).
        rank += (kq < kv) || (kq == kv && q < p);
    }
    g_sorted[start + rank] = v;
}

// ---------------- 6) density + finalize (1 block, 1024 threads) -----------------
__global__ void density_finalize_kernel(float* __restrict__ out) {
    __shared__ float r_sum[32], r_max[32], r_mse[32], r_d2[32];
    int tid = threadIdx.x;
    int lane = tid & 31;
    int wid = tid >> 5;

    float dsum = 0.0f, dmax = -FLT_MAX;
#pragma unroll
    for (int i = tid; i < N; i += 1024) {
        float xi = g_sorted[i];
        float c0 = (i >= 1)     ? xi - g_sorted[i - 1] : FLT_MAX;
        float c1 = (i >= 2)     ? xi - g_sorted[i - 2] : FLT_MAX;
        float c2 = (i + 1 < N)  ? g_sorted[i + 1] - xi : FLT_MAX;
        float c3 = (i + 2 < N)  ? g_sorted[i + 2] - xi : FLT_MAX;
        float m1 = fminf(c0, c2);
        float m2 = (c0 < c2) ? fminf(c1, c2) : fminf(c0, c3);
        // knn vals = {EPS, m1+EPS, m2+EPS}
        float knn_mean = (m1 + m2 + 3.0f * EPSF) * (1.0f / 3.0f);
        float dens = 1.0f / (knn_mean + EPSF);
        dsum += dens;
        dmax = fmaxf(dmax, dens);
    }

    float vm = (tid < NBLK) ? g_pmse[tid] : 0.0f;
    float vd = (tid < NBLK) ? g_pd2[tid] : 0.0f;

    dsum = warp_sum(dsum);
    dmax = warp_max(dmax);
    vm = warp_sum(vm);
    vd = warp_sum(vd);
    if (lane == 0) { r_sum[wid] = dsum; r_max[wid] = dmax; r_mse[wid] = vm; r_d2[wid] = vd; }
    __syncthreads();
    if (wid == 0) {
        float s = r_sum[lane];
        float x2 = r_max[lane];
        float m = r_mse[lane];
        float d = r_d2[lane];
        s = warp_sum(s);
        x2 = warp_max(x2);
        m = warp_sum(m);
        d = warp_sum(d);
        if (lane == 0) {
            float mse = m * (1.0f / N);
            float md2 = d * (1.0f / N);
            float mean_dnorm = (s * (1.0f / N)) / (x2 + EPSF);
            float mean_w = 1.0f + 0.1f * mean_dnorm;
            float penalty = 0.01f * mean_w * md2;
            out[0] = mse + penalty;
            out[1] = mse;
            out[2] = penalty;
        }
    }
}

// ---------------- launch --------------------------------------------------------
extern "C" void kernel_launch(void* const* d_in, const int* in_sizes, int n_in,
                              void* d_out, int out_size) {
    const float* x   = (const float*)d_in[0];
    const float* tgt = (const float*)d_in[1];
    const float* w1  = (const float*)d_in[2];
    const float* b1  = (const float*)d_in[3];
    const float* w2  = (const float*)d_in[4];
    const float* b2  = (const float*)d_in[5];
    float* out = (float*)d_out;

    mlp_zero_kernel<<<NBLK, TPB>>>(x, tgt, w1, b1, w2, b2);  // also zeros g_cnt
    hist_kernel<<<128, 128>>>(x);
    scan_kernel<<<1, SCAN_T>>>();
    scatter_kernel<<<128, 128>>>(x);
    rank_kernel<<<128, 128>>>();
    density_finalize_kernel<<<1, 1024>>>(out);
    (void)in_sizes; (void)n_in; (void)out_size;
}

// round 4
// speedup vs baseline: 6.5962x; 5.8371x over previous
#include <cuda_runtime.h>
#include <float.h>

#define N 16384
#define H 64
#define EPSF 1e-8f
#define NBLK 128
#define TPB 128
#define NB 65536            // buckets = top 16 bits of order-preserving key

// ---------------- scratch (device globals; no allocation allowed) ------------
__device__ float g_tmp[N];     // scattered (bucket-grouped) values
__device__ float g_sorted[N];  // fully sorted
__device__ int   g_cnt[NB];    // zeroed by mlp_zero_kernel each replay
__device__ int   g_off[NB];    // block-local exclusive prefix; mutated by scatter
__device__ int   g_start[NB];  // pristine block-local exclusive prefix
__device__ int   g_btot[64];   // per-scan-block totals
__device__ int   g_bbase[64];  // exclusive scan of block totals
__device__ float g_pmse[NBLK];
__device__ float g_pd2[NBLK];

// ---------------- helpers -----------------------------------------------------
__device__ __forceinline__ float warp_sum(float v) {
#pragma unroll
    for (int o = 16; o > 0; o >>= 1) v += __shfl_xor_sync(0xffffffffu, v, o);
    return v;
}
__device__ __forceinline__ float warp_max(float v) {
#pragma unroll
    for (int o = 16; o > 0; o >>= 1) v = fmaxf(v, __shfl_xor_sync(0xffffffffu, v, o));
    return v;
}
// order-preserving float -> uint key (total order == float order for non-NaN)
__device__ __forceinline__ unsigned int okey(float f) {
    unsigned int u = __float_as_uint(f);
    return (u & 0x80000000u) ? ~u : (u | 0x80000000u);
}

// ---------------- 1) MLP partials + zero the bucket counters -----------------
__global__ void mlp_zero_kernel(const float* __restrict__ x,
                                const float* __restrict__ tgt,
                                const float* __restrict__ w1,
                                const float* __restrict__ b1,
                                const float* __restrict__ w2,
                                const float* __restrict__ b2) {
    // zero g_cnt: 16384 threads x int4 = 65536 ints
    int gi = blockIdx.x * TPB + threadIdx.x;
    reinterpret_cast<int4*>(g_cnt)[gi] = make_int4(0, 0, 0, 0);

    __shared__ float sw1[H], sb1[H], sw2[H], sc2[H];
    __shared__ float red_mse[TPB / 32], red_d2[TPB / 32];

    int tid = threadIdx.x;
    if (tid < H) {
        float a = w1[tid];
        float c = w2[tid];
        sw1[tid] = a;
        sb1[tid] = b1[tid];
        sw2[tid] = c;
        sc2[tid] = -2.0f * c * a * a;   // coeff of t*(1-t^2) in d2y/dx2
    }
    __syncthreads();

    float xv = x[gi];
    float pred = b2[0];
    float d2 = 0.0f;
#pragma unroll
    for (int h = 0; h < H; ++h) {
        float t = tanhf(fmaf(xv, sw1[h], sb1[h]));
        pred = fmaf(sw2[h], t, pred);
        float g = t * fmaf(-t, t, 1.0f);        // t - t^3
        d2 = fmaf(sc2[h], g, d2);
    }
    float e = pred - tgt[gi];
    float vm = e * e;
    float vd = d2 * d2;

    vm = warp_sum(vm);
    vd = warp_sum(vd);
    if ((tid & 31) == 0) { red_mse[tid >> 5] = vm; red_d2[tid >> 5] = vd; }
    __syncthreads();
    if (tid < 32) {
        float m = (tid < TPB / 32) ? red_mse[tid] : 0.0f;
        float d = (tid < TPB / 32) ? red_d2[tid] : 0.0f;
        m = warp_sum(m);
        d = warp_sum(d);
        if (tid == 0) { g_pmse[blockIdx.x] = m; g_pd2[blockIdx.x] = d; }
    }
}

// ---------------- 2) histogram -------------------------------------------------
__global__ void hist_kernel(const float* __restrict__ x) {
    int i = blockIdx.x * blockDim.x + threadIdx.x;
    unsigned int b = okey(x[i]) >> 16;
    atomicAdd(&g_cnt[b], 1);
}

// ---------------- 3a) per-block coalesced scan (64 blocks x 1024 buckets) ------
__global__ void scan1_kernel() {
    __shared__ int wsum[8];
    int tid = threadIdx.x;              // 256 threads
    int lane = tid & 31;
    int wid = tid >> 5;
    int idx = blockIdx.x * 256 + tid;   // int4 index into g_cnt

    int4 c4 = reinterpret_cast<const int4*>(g_cnt)[idx];
    int s = c4.x + c4.y + c4.z + c4.w;

    // warp inclusive scan of s
    int inc = s;
#pragma unroll
    for (int o = 1; o < 32; o <<= 1) {
        int nb = __shfl_up_sync(0xffffffffu, inc, o);
        if (lane >= o) inc += nb;
    }
    if (lane == 31) wsum[wid] = inc;
    __syncthreads();
    if (wid == 0 && lane < 8) {
        int v = wsum[lane];
        int wi = v;
#pragma unroll
        for (int o = 1; o < 8; o <<= 1) {
            int nb = __shfl_up_sync(0x000000ffu, wi, o);
            if (lane >= o) wi += nb;
        }
        wsum[lane] = wi - v;   // exclusive warp offsets
    }
    __syncthreads();

    int e = wsum[wid] + (inc - s);   // block-local exclusive base for this thread
    int4 o4;
    o4.x = e;
    o4.y = e + c4.x;
    o4.z = o4.y + c4.y;
    o4.w = o4.z + c4.z;
    reinterpret_cast<int4*>(g_off)[idx] = o4;
    reinterpret_cast<int4*>(g_start)[idx] = o4;
    if (tid == 255) g_btot[blockIdx.x] = e + s;  // block total
}

// ---------------- 3b) scan of 64 block totals (1 warp) --------------------------
__global__ void scan2_kernel() {
    int lane = threadIdx.x;  // 32 threads, each owns 2 consecutive totals
    int t0 = g_btot[2 * lane];
    int t1 = g_btot[2 * lane + 1];
    int s = t0 + t1;
    int inc = s;
#pragma unroll
    for (int o = 1; o < 32; o <<= 1) {
        int nb = __shfl_up_sync(0xffffffffu, inc, o);
        if (lane >= o) inc += nb;
    }
    int excl = inc - s;
    g_bbase[2 * lane] = excl;
    g_bbase[2 * lane + 1] = excl + t0;
}

// ---------------- 4) scatter (bucket-group, order within bucket arbitrary) ------
__global__ void scatter_kernel(const float* __restrict__ x) {
    int i = blockIdx.x * blockDim.x + threadIdx.x;
    float xv = x[i];
    unsigned int b = okey(xv) >> 16;
    int pos = atomicAdd(&g_off[b], 1) + g_bbase[b >> 10];
    g_tmp[pos] = xv;
}

// ---------------- 5) parallel rank-in-segment -----------------------------------
__global__ void rank_kernel() {
    int p = blockIdx.x * blockDim.x + threadIdx.x;  // position in scattered array
    float v = g_tmp[p];
    unsigned int kv = okey(v);
    unsigned int b = kv >> 16;
    int start = g_start[b] + g_bbase[b >> 10];
    int end = start + g_cnt[b];
    int rank = 0;
    for (int q = start; q < end; ++q) {
        unsigned int kq = okey(g_tmp[q]);
        // equal keys are bit-identical floats: tie-break keeps ranks a permutation,
        // final sorted contents deterministic regardless of scatter order.
        rank += (kq < kv) || (kq == kv && q < p);
    }
    g_sorted[start + rank] = v;
}

// ---------------- 6) density + finalize (1 block, 1024 threads) -----------------
__global__ void density_finalize_kernel(float* __restrict__ out) {
    __shared__ float r_sum[32], r_max[32], r_mse[32], r_d2[32];
    int tid = threadIdx.x;
    int lane = tid & 31;
    int wid = tid >> 5;

    float dsum = 0.0f, dmax = -FLT_MAX;
#pragma unroll
    for (int i = tid; i < N; i += 1024) {
        float xi = g_sorted[i];
        float c0 = (i >= 1)     ? xi - g_sorted[i - 1] : FLT_MAX;
        float c1 = (i >= 2)     ? xi - g_sorted[i - 2] : FLT_MAX;
        float c2 = (i + 1 < N)  ? g_sorted[i + 1] - xi : FLT_MAX;
        float c3 = (i + 2 < N)  ? g_sorted[i + 2] - xi : FLT_MAX;
        float m1 = fminf(c0, c2);
        float m2 = (c0 < c2) ? fminf(c1, c2) : fminf(c0, c3);
        // knn vals = {EPS, m1+EPS, m2+EPS}
        float knn_mean = (m1 + m2 + 3.0f * EPSF) * (1.0f / 3.0f);
        float dens = 1.0f / (knn_mean + EPSF);
        dsum += dens;
        dmax = fmaxf(dmax, dens);
    }

    float vm = (tid < NBLK) ? g_pmse[tid] : 0.0f;
    float vd = (tid < NBLK) ? g_pd2[tid] : 0.0f;

    dsum = warp_sum(dsum);
    dmax = warp_max(dmax);
    vm = warp_sum(vm);
    vd = warp_sum(vd);
    if (lane == 0) { r_sum[wid] = dsum; r_max[wid] = dmax; r_mse[wid] = vm; r_d2[wid] = vd; }
    __syncthreads();
    if (wid == 0) {
        float s = r_sum[lane];
        float x2 = r_max[lane];
        float m = r_mse[lane];
        float d = r_d2[lane];
        s = warp_sum(s);
        x2 = warp_max(x2);
        m = warp_sum(m);
        d = warp_sum(d);
        if (lane == 0) {
            float mse = m * (1.0f / N);
            float md2 = d * (1.0f / N);
            float mean_dnorm = (s * (1.0f / N)) / (x2 + EPSF);
            float mean_w = 1.0f + 0.1f * mean_dnorm;
            float penalty = 0.01f * mean_w * md2;
            out[0] = mse + penalty;
            out[1] = mse;
            out[2] = penalty;
        }
    }
}

// ---------------- launch --------------------------------------------------------
extern "C" void kernel_launch(void* const* d_in, const int* in_sizes, int n_in,
                              void* d_out, int out_size) {
    const float* x   = (const float*)d_in[0];
    const float* tgt = (const float*)d_in[1];
    const float* w1  = (const float*)d_in[2];
    const float* b1  = (const float*)d_in[3];
    const float* w2  = (const float*)d_in[4];
    const float* b2  = (const float*)d_in[5];
    float* out = (float*)d_out;

    mlp_zero_kernel<<<NBLK, TPB>>>(x, tgt, w1, b1, w2, b2);  // also zeros g_cnt
    hist_kernel<<<128, 128>>>(x);
    scan1_kernel<<<64, 256>>>();
    scan2_kernel<<<1, 32>>>();
    scatter_kernel<<<128, 128>>>(x);
    rank_kernel<<<128, 128>>>();
    density_finalize_kernel<<<1, 1024>>>(out);
    (void)in_sizes; (void)n_in; (void)out_size;
}

// round 5
// speedup vs baseline: 7.7597x; 1.1764x over previous
#include <cuda_runtime.h>
#include <float.h>

#define N 16384
#define H 64
#define EPSF 1e-8f
#define GRID 128
#define TPB 128
#define NB 65536  // buckets = top 16 bits of order-preserving key

// ---------------- scratch (device globals; no allocation allowed) ------------
__device__ float g_tmp[N];      // scattered (bucket-grouped) values
__device__ float g_sorted[N];   // fully sorted
__device__ int   g_cnt[NB];     // INVARIANT: zero at kernel entry; re-zeroed before exit
__device__ int   g_off[NB];     // absolute exclusive prefix; mutated by scatter
__device__ int   g_start[NB];   // pristine absolute exclusive prefix
__device__ int   g_btot[GRID];  // per-block bucket-count totals
__device__ float g_pmse[GRID], g_pd2[GRID], g_pdens[GRID], g_pdmax[GRID];
__device__ unsigned g_arrive = 0;   // barrier arrival counter (self-resetting)
__device__ unsigned g_epoch = 0;    // barrier epoch (monotonic, wrap-safe compare)

// ---------------- helpers -----------------------------------------------------
__device__ __forceinline__ float warp_sum(float v) {
#pragma unroll
    for (int o = 16; o > 0; o >>= 1) v += __shfl_xor_sync(0xffffffffu, v, o);
    return v;
}
__device__ __forceinline__ float warp_max(float v) {
#pragma unroll
    for (int o = 16; o > 0; o >>= 1) v = fmaxf(v, __shfl_xor_sync(0xffffffffu, v, o));
    return v;
}
__device__ __forceinline__ unsigned int okey(float f) {
    unsigned int u = __float_as_uint(f);
    return (u & 0x80000000u) ? ~u : (u | 0x80000000u);
}

// grid-wide barrier: all GRID blocks must be co-resident (GRID=128 < 148 SMs).
// __threadfence (gpu scope) both orders this block's writes into L2 and emits
// CCTL.IVALL, invalidating this SM's L1D so post-barrier loads refetch from L2.
__device__ __forceinline__ void grid_sync(unsigned base, unsigned ph) {
    __syncthreads();
    if (threadIdx.x == 0) {
        __threadfence();
        unsigned a = atomicAdd(&g_arrive, 1);
        if (a == GRID - 1) {
            atomicExch(&g_arrive, 0);   // reset for next barrier
            __threadfence();
            atomicAdd(&g_epoch, 1);     // release
        } else {
            while ((*(volatile unsigned*)&g_epoch) - base < ph) { }
        }
    }
    __syncthreads();
}

// block reduce (TPB=128 -> 4 warps) helpers using a 4-slot smem array
__device__ __forceinline__ float block_sum(float v, float* s4) {
    int lane = threadIdx.x & 31, wid = threadIdx.x >> 5;
    v = warp_sum(v);
    if (lane == 0) s4[wid] = v;
    __syncthreads();
    float r = (lane < 4) ? s4[lane] : 0.0f;
    r = warp_sum(r);  // all lanes of each warp compute same; take warp 0 value via smem
    __syncthreads();
    return r;
}

__global__ void __launch_bounds__(TPB, 1)
fused_kernel(const float* __restrict__ x,   const float* __restrict__ tgt,
             const float* __restrict__ w1,  const float* __restrict__ b1,
             const float* __restrict__ w2,  const float* __restrict__ b2,
             float* __restrict__ out) {
    __shared__ float sw1[H], sb1[H], sw2[H], sc2[H];
    __shared__ float sA[4], sB[4];
    __shared__ int   sI[4];
    __shared__ int   swarp[4];
    __shared__ unsigned s_base;

    const int tid = threadIdx.x;
    const int blk = blockIdx.x;
    const int gi  = blk * TPB + tid;
    const int lane = tid & 31, wid = tid >> 5;

    if (tid == 0) s_base = *(volatile unsigned*)&g_epoch;  // before any barrier completes

    if (tid < H) {
        float a = w1[tid];
        float c = w2[tid];
        sw1[tid] = a; sb1[tid] = b1[tid]; sw2[tid] = c;
        sc2[tid] = -2.0f * c * a * a;
    }
    __syncthreads();
    const unsigned base = s_base;

    // ---------------- phase 0: MLP partials + histogram ----------------
    const float xv = x[gi];
    float pred = b2[0];
    float d2 = 0.0f;
#pragma unroll
    for (int h = 0; h < H; ++h) {
        float t = tanhf(fmaf(xv, sw1[h], sb1[h]));
        pred = fmaf(sw2[h], t, pred);
        float g = t * fmaf(-t, t, 1.0f);
        d2 = fmaf(sc2[h], g, d2);
    }
    {
        float e = pred - tgt[gi];
        float vm = warp_sum(e * e);
        float vd = warp_sum(d2 * d2);
        if (lane == 0) { sA[wid] = vm; sB[wid] = vd; }
        __syncthreads();
        if (tid == 0) {
            g_pmse[blk] = sA[0] + sA[1] + sA[2] + sA[3];
            g_pd2[blk]  = sB[0] + sB[1] + sB[2] + sB[3];
        }
    }
    const unsigned key = okey(xv);
    const unsigned b = key >> 16;
    atomicAdd(&g_cnt[b], 1);      // g_cnt zero at entry (invariant)

    grid_sync(base, 1);

    // ---------------- phase 1a: block-local scan of 4 buckets/thread ----------
    int4 c4 = reinterpret_cast<const int4*>(g_cnt)[gi];
    int s = c4.x + c4.y + c4.z + c4.w;
    int inc = s;
#pragma unroll
    for (int o = 1; o < 32; o <<= 1) {
        int nb = __shfl_up_sync(0xffffffffu, inc, o);
        if (lane >= o) inc += nb;
    }
    if (lane == 31) swarp[wid] = inc;
    __syncthreads();
    if (wid == 0 && lane < 4) {
        int v = swarp[lane];
        int wi = v;
#pragma unroll
        for (int o = 1; o < 4; o <<= 1) {
            int nb = __shfl_up_sync(0x0000000fu, wi, o);
            if (lane >= o) wi += nb;
        }
        swarp[lane] = wi - v;   // exclusive warp offsets
    }
    __syncthreads();
    int e_blk = swarp[wid] + (inc - s);     // block-local exclusive base
    if (tid == TPB - 1) g_btot[blk] = e_blk + s;  // block total

    grid_sync(base, 2);

    // ---------------- phase 1b: absolute offsets --------------------------------
    {
        int v = (tid < blk) ? g_btot[tid] : 0;
        float dummy;  // integer block sum via warp shuffles
        int ws = v;
#pragma unroll
        for (int o = 16; o > 0; o >>= 1) ws += __shfl_xor_sync(0xffffffffu, ws, o);
        if (lane == 0) sI[wid] = ws;
        __syncthreads();
        int bbase = sI[0] + sI[1] + sI[2] + sI[3];
        int4 o4;
        o4.x = bbase + e_blk;
        o4.y = o4.x + c4.x;
        o4.z = o4.y + c4.y;
        o4.w = o4.z + c4.z;
        reinterpret_cast<int4*>(g_off)[gi] = o4;
        reinterpret_cast<int4*>(g_start)[gi] = o4;
        (void)dummy;
    }

    grid_sync(base, 3);

    // ---------------- phase 2: scatter ------------------------------------------
    {
        int pos = atomicAdd(&g_off[b], 1);
        g_tmp[pos] = xv;
    }

    grid_sync(base, 4);

    // ---------------- phase 3: rank-in-segment ----------------------------------
    {
        float v = g_tmp[gi];
        unsigned kv = okey(v);
        unsigned bb = kv >> 16;
        int st = g_start[bb];
        int en = st + g_cnt[bb];
        int r = 0;
        for (int q = st; q < en; ++q) {
            unsigned kq = okey(g_tmp[q]);
            // equal keys are bit-identical floats: final contents deterministic
            r += (kq < kv) || (kq == kv && q < gi);
        }
        g_sorted[st + r] = v;
    }

    grid_sync(base, 5);

    // ---------------- phase 4: density + restore g_cnt zero-invariant -----------
    reinterpret_cast<int4*>(g_cnt)[gi] = make_int4(0, 0, 0, 0);
    {
        float xi = g_sorted[gi];
        float c0 = (gi >= 1)     ? xi - g_sorted[gi - 1] : FLT_MAX;
        float c1 = (gi >= 2)     ? xi - g_sorted[gi - 2] : FLT_MAX;
        float c2 = (gi + 1 < N)  ? g_sorted[gi + 1] - xi : FLT_MAX;
        float c3 = (gi + 2 < N)  ? g_sorted[gi + 2] - xi : FLT_MAX;
        float m1 = fminf(c0, c2);
        float m2 = (c0 < c2) ? fminf(c1, c2) : fminf(c0, c3);
        float knn_mean = (m1 + m2 + 3.0f * EPSF) * (1.0f / 3.0f);
        float dens = 1.0f / (knn_mean + EPSF);

        float vs = warp_sum(dens);
        float vx = warp_max(dens);
        if (lane == 0) { sA[wid] = vs; sB[wid] = vx; }
        __syncthreads();
        if (tid == 0) {
            g_pdens[blk] = sA[0] + sA[1] + sA[2] + sA[3];
            g_pdmax[blk] = fmaxf(fmaxf(sA[0] * 0.0f + sB[0], sB[1]), fmaxf(sB[2], sB[3]));
        }
    }

    grid_sync(base, 6);

    // ---------------- phase 5: finalize (block 0) --------------------------------
    if (blk == 0) {
        float vm = g_pmse[tid];
        float vd = g_pd2[tid];
        float vs = g_pdens[tid];
        float vx = g_pdmax[tid];
        vm = warp_sum(vm);
        vd = warp_sum(vd);
        vs = warp_sum(vs);
        vx = warp_max(vx);
        if (lane == 0) { sA[wid] = vm; sB[wid] = vd; sw1[wid] = vs; sw2[wid] = vx; }
        __syncthreads();
        if (tid == 0) {
            float mse  = (sA[0] + sA[1] + sA[2] + sA[3]) * (1.0f / N);
            float md2  = (sB[0] + sB[1] + sB[2] + sB[3]) * (1.0f / N);
            float dsum = (sw1[0] + sw1[1] + sw1[2] + sw1[3]);
            float dmax = fmaxf(fmaxf(sw2[0], sw2[1]), fmaxf(sw2[2], sw2[3]));
            float mean_dnorm = (dsum * (1.0f / N)) / (dmax + EPSF);
            float mean_w = 1.0f + 0.1f * mean_dnorm;
            float penalty = 0.01f * mean_w * md2;
            out[0] = mse + penalty;
            out[1] = mse;
            out[2] = penalty;
        }
    }
}

// ---------------- launch --------------------------------------------------------
extern "C" void kernel_launch(void* const* d_in, const int* in_sizes, int n_in,
                              void* d_out, int out_size) {
    const float* x   = (const float*)d_in[0];
    const float* tgt = (const float*)d_in[1];
    const float* w1  = (const float*)d_in[2];
    const float* b1  = (const float*)d_in[3];
    const float* w2  = (const float*)d_in[4];
    const float* b2  = (const float*)d_in[5];
    float* out = (float*)d_out;

    fused_kernel<<<GRID, TPB>>>(x, tgt, w1, b1, w2, b2, out);
    (void)in_sizes; (void)n_in; (void)out_size;
}